// round 16
// baseline (speedup 1.0000x reference)
#include <cuda_runtime.h>
#include <cstdint>

// ---------------- problem constants ----------------
#define N_CB 4
#define M_CODES 512
#define D_DIM 32
#define T_POS 65536

// output layout (float32, reference tuple order, flattened+concatenated)
#define OFF_ZQ   0ULL
#define OFF_LOSS 8388608ULL
#define OFF_PERP 8388609ULL
#define OFF_IDX  8388610ULL
#define OFF_EMB  8650754ULL
#define OFF_CNT  8716290ULL
#define OFF_W    8718338ULL

// fragment-permuted slot: d = kt*8 + 4*h + q4  ->  slot = q4*8 + kt*2 + h
#define SLOT(d) (((d) & 3) * 8 + ((d) >> 3) * 2 + (((d) >> 2) & 1))

// ---------------- smem layout (float offsets) ----------------
#define SXP_F   0        // x [128 pos][36] slot-permuted          4608
#define SE_F    4608     // e lane-major fragments [64 nt][256]   16384
#define SESQ_F  20992    // esq[512]
#define SXSQ_F  21504    // xsq[128]
#define SSAB_F  21632    // sum|x| [128]
#define SBEST_F 21760    // u64[128] packed (dist,code)
#define SQ1_F   22016    // singles queue u32[512]
#define SFL_F   22528    // range-flag queue u32[256]
#define SWS_F   22784    // warp loss partials [8]
#define SMEM_FLOATS 22792
#define SMEM_BYTES (SMEM_FLOATS * 4)   // 91168 -> 2 CTAs/SM

#define FLT_BIG 3.402823466e38f
#define MARG_COEF 1.6e-4f
#define MARG_ABS  5e-5f
#define FCAP 256

// ---------------- scratch (zero at load; finalize kernels re-zero after use) ----------------
__device__ int    g_counts[N_CB * M_CODES];
__device__ float4 g_dw4[N_CB * M_CODES * 8];
__device__ double g_loss;
__device__ float  g_clap[N_CB * M_CODES];

// ---------------- kernel 1 ----------------
__global__ void __launch_bounds__(256) vq_main(const float* __restrict__ x,
                                               const float* __restrict__ emb,
                                               float* __restrict__ out) {
    extern __shared__ float sm[];
    __shared__ int qn1, fn;
    float* sX   = sm + SXP_F;
    float* sE   = sm + SE_F;
    float* sEsq = sm + SESQ_F;
    float* sXsq = sm + SXSQ_F;
    float* sSab = sm + SSAB_F;
    unsigned long long* sBest = (unsigned long long*)(sm + SBEST_F);
    unsigned int* sQ1 = (unsigned int*)(sm + SQ1_F);
    unsigned int* sFl = (unsigned int*)(sm + SFL_F);
    float* sWs  = sm + SWS_F;

    const int n    = blockIdx.y;
    const int tile = blockIdx.x;
    const int tid  = threadIdx.x;
    const int w    = tid >> 5;
    const int lane = tid & 31;
    const int g    = lane >> 2;
    const int q4   = lane & 3;

    if (tile == 0 && n == 0 && tid == 0) out[OFF_PERP] = 0.0f;

    // ---- fill x tile (slot-permuted) ----
    for (int i = tid; i < 128 * D_DIM; i += 256) {
        int d = i >> 7, p = i & 127;
        int t = tile * 128 + p;
        sX[p * 36 + SLOT(d)] = x[(size_t)(t >> 6) * 8192 + (size_t)n * 2048 + d * 64 + (t & 63)];
    }
    // ---- fill codebook: lane-major fragments + bit4 XOR swizzle (conflict-free STS) ----
    const float* en = emb + (size_t)n * M_CODES * D_DIM;
    for (int i = tid; i < M_CODES * D_DIM; i += 256) {
        int m = i >> 5, d = i & 31;
        int gg = m & 7, ntt = m >> 3;
        sE[ntt * 256 + ((gg * 32 + SLOT(d)) ^ ((gg & 1) * 4))] = en[i];
    }
    if (tid == 0) { qn1 = 0; fn = 0; }
    __syncthreads();

    // ---- esq: warp-cooperative, conflict-free (warp w -> codes [64w,64w+64)) ----
    for (int it = 0; it < 16; it++) {
        int c = w * 64 + it * 4 + (lane >> 3);
        int d4 = lane & 7;
        const float* ep = sE + ((c >> 3) << 8) + ((c & 7) * 32);
        float4 ev = *(const float4*)(ep + ((d4 * 4) ^ ((c & 1) * 4)));
        float pq = ev.x * ev.x;
        pq = fmaf(ev.y, ev.y, pq);
        pq = fmaf(ev.z, ev.z, pq);
        pq = fmaf(ev.w, ev.w, pq);
        pq += __shfl_xor_sync(0xFFFFFFFFu, pq, 1);
        pq += __shfl_xor_sync(0xFFFFFFFFu, pq, 2);
        pq += __shfl_xor_sync(0xFFFFFFFFu, pq, 4);
        if (d4 == 0) sEsq[c] = pq;
    }
    // ---- xsq + sum|x| + sBest init ----
    if (tid < 128) {
        const float* xr = sX + tid * 36;
        float s = 0.0f, a = 0.0f;
#pragma unroll
        for (int d = 0; d < D_DIM; d++) {
            float v = xr[SLOT(d)];
            s = fmaf(v, v, s);
            a += fabsf(v);
        }
        sXsq[tid] = s;
        sSab[tid] = a;
        sBest[tid] = 0xFFFFFFFFFFFFFFFFull;
    }
    __syncthreads();

    // ---- A fragments ----
    const int r0 = w * 16 + g;
    const int r1 = r0 + 8;
    float4 xa0 = *(const float4*)&sX[r0 * 36 + q4 * 8];
    float4 xa1 = *(const float4*)&sX[r0 * 36 + q4 * 8 + 4];
    float4 xb0 = *(const float4*)&sX[r1 * 36 + q4 * 8];
    float4 xb1 = *(const float4*)&sX[r1 * 36 + q4 * 8 + 4];
    float af0[4], af1[4], af2[4], af3[4];
    af0[0] = xa0.x; af2[0] = xa0.y; af0[1] = xa0.z; af2[1] = xa0.w;
    af0[2] = xa1.x; af2[2] = xa1.y; af0[3] = xa1.z; af2[3] = xa1.w;
    af1[0] = xb0.x; af3[0] = xb0.y; af1[1] = xb0.z; af3[1] = xb0.w;
    af1[2] = xb1.x; af3[2] = xb1.y; af1[3] = xb1.z; af3[3] = xb1.w;

    // conflict-free B-fragment pointers (bit4 XOR swizzle)
    const float* pe0 = sE + lane * 8 + (lane & 4);        // j = 0..3
    const float* pe1 = sE + lane * 8 + 4 - (lane & 4);    // j = 4..7

    // ---- single branchless sweep: split accumulator chains, top-2 per row ----
    float m1_0 = FLT_BIG, m2_0 = FLT_BIG, m1_1 = FLT_BIG, m2_1 = FLT_BIG;
    int   i1_0 = 0, i1_1 = 0;

#pragma unroll 4
    for (int nt = 0; nt < 64; nt++) {
        float a0 = 0.0f, a1 = 0.0f, a2 = 0.0f, a3 = 0.0f;
        float b0 = 0.0f, b1 = 0.0f, b2 = 0.0f, b3 = 0.0f;
        {
            float4 e0 = *(const float4*)(pe0 + nt * 256);
            float4 e1 = *(const float4*)(pe1 + nt * 256);
            float bbf[8] = {e0.x, e0.y, e0.z, e0.w, e1.x, e1.y, e1.z, e1.w};
#pragma unroll
            for (int kt = 0; kt < 2; kt++) {
                asm volatile(
                    "mma.sync.aligned.m16n8k8.row.col.f32.tf32.tf32.f32 "
                    "{%0,%1,%2,%3}, {%4,%5,%6,%7}, {%8,%9}, {%0,%1,%2,%3};"
                    : "+f"(a0), "+f"(a1), "+f"(a2), "+f"(a3)
                    : "f"(af0[kt]), "f"(af1[kt]), "f"(af2[kt]), "f"(af3[kt]),
                      "f"(bbf[2 * kt]), "f"(bbf[2 * kt + 1]));
            }
#pragma unroll
            for (int kt = 2; kt < 4; kt++) {
                asm volatile(
                    "mma.sync.aligned.m16n8k8.row.col.f32.tf32.tf32.f32 "
                    "{%0,%1,%2,%3}, {%4,%5,%6,%7}, {%8,%9}, {%0,%1,%2,%3};"
                    : "+f"(b0), "+f"(b1), "+f"(b2), "+f"(b3)
                    : "f"(af0[kt]), "f"(af1[kt]), "f"(af2[kt]), "f"(af3[kt]),
                      "f"(bbf[2 * kt]), "f"(bbf[2 * kt + 1]));
            }
        }
        float c0 = a0 + b0, c1 = a1 + b1, c2 = a2 + b2, c3 = a3 + b3;

        const int col0 = nt * 8 + q4 * 2;
        float2 e2 = *(const float2*)&sEsq[col0];
        float d00 = fmaf(c0, -2.0f, e2.x);
        float d01 = fmaf(c1, -2.0f, e2.y);
        float d10 = fmaf(c2, -2.0f, e2.x);
        float d11 = fmaf(c3, -2.0f, e2.y);

        {   // row 0
            float lo = fminf(d00, d01);
            float hi = fmaxf(d00, d01);
            int  ilo = (d01 < d00) ? (col0 + 1) : col0;
            m2_0 = fminf(m2_0, fminf(hi, fmaxf(lo, m1_0)));
            i1_0 = (lo < m1_0) ? ilo : i1_0;
            m1_0 = fminf(m1_0, lo);
        }
        {   // row 1
            float lo = fminf(d10, d11);
            float hi = fmaxf(d10, d11);
            int  ilo = (d11 < d10) ? (col0 + 1) : col0;
            m2_1 = fminf(m2_1, fminf(hi, fmaxf(lo, m1_1)));
            i1_1 = (lo < m1_1) ? ilo : i1_1;
            m1_1 = fminf(m1_1, lo);
        }
    }

    const float lm1_0 = m1_0, lm2_0 = m2_0, lm1_1 = m1_1, lm2_1 = m2_1;
    const int   li1_0 = i1_0, li1_1 = i1_1;

    // ---- merge across the 4 quad-threads of each row ----
#pragma unroll
    for (int o = 1; o <= 2; o <<= 1) {
        float om1 = __shfl_xor_sync(0xFFFFFFFFu, m1_0, o);
        float om2 = __shfl_xor_sync(0xFFFFFFFFu, m2_0, o);
        m2_0 = fminf(fminf(m2_0, om2), fmaxf(m1_0, om1));
        m1_0 = fminf(m1_0, om1);
        float pm1 = __shfl_xor_sync(0xFFFFFFFFu, m1_1, o);
        float pm2 = __shfl_xor_sync(0xFFFFFFFFu, m2_1, o);
        m2_1 = fminf(fminf(m2_1, pm2), fmaxf(m1_1, pm1));
        m1_1 = fminf(m1_1, pm1);
    }
    const float thr0 = m1_0 + fmaf(sSab[r0], MARG_COEF, MARG_ABS);
    const float thr1 = m1_1 + fmaf(sSab[r1], MARG_COEF, MARG_ABS);

    // ---- queue candidates (singles + flagged ranges) ----
    if (lm1_0 <= thr0) { int s = atomicAdd(&qn1, 1); sQ1[s] = (r0 << 9) | li1_0; }
    if (lm1_1 <= thr1) { int s = atomicAdd(&qn1, 1); sQ1[s] = (r1 << 9) | li1_1; }
    if (lm2_0 <= thr0) { int s = atomicAdd(&fn, 1); if (s < FCAP) sFl[s] = (r0 << 2) | q4; }
    if (lm2_1 <= thr1) { int s = atomicAdd(&fn, 1); if (s < FCAP) sFl[s] = (r1 << 2) | q4; }
    __syncthreads();

    // ---- warp-cooperative exact fp32 recheck (conflict-free smem) ----
#define COOP_CHECK(rowv, codev, valid) {                                          \
        int d4c = lane & 7;                                                       \
        const float* epc = sE + (((codev) >> 3) << 8) + (((codev) & 7) * 32);     \
        float4 ev = *(const float4*)(epc + ((d4c * 4) ^ (((codev) & 1) * 4)));    \
        float4 xv = *(const float4*)(sX + (rowv) * 36 + d4c * 4);                 \
        float pq = xv.x * ev.x;                                                   \
        pq = fmaf(xv.y, ev.y, pq);                                                \
        pq = fmaf(xv.z, ev.z, pq);                                                \
        pq = fmaf(xv.w, ev.w, pq);                                                \
        pq += __shfl_xor_sync(0xFFFFFFFFu, pq, 1);                                \
        pq += __shfl_xor_sync(0xFFFFFFFFu, pq, 2);                                \
        pq += __shfl_xor_sync(0xFFFFFFFFu, pq, 4);                                \
        if (d4c == 0 && (valid)) {                                                \
            float dist = fmaf(pq, -2.0f, sXsq[rowv] + sEsq[codev]);               \
            unsigned long long pk =                                               \
                ((unsigned long long)__float_as_uint(dist) << 32)                 \
                | (unsigned int)(codev);                                          \
            atomicMin(&sBest[rowv], pk);                                          \
        }                                                                         \
    }

    {   // singles: 4 entries per warp-iteration
        const int nq = qn1;
        const int niter = (nq + 3) >> 2;
        for (int i = w; i < niter; i += 8) {
            int ei = i * 4 + (lane >> 3);
            int eic = (ei < nq) ? ei : (nq - 1);
            unsigned int ent = sQ1[eic];
            int row = ent >> 9, code = ent & 511;
            COOP_CHECK(row, code, ei < nq)
        }
    }
    {   // flagged ranges: 4 codes per warp-iteration, 32 iters per range
        const int nf = (fn < FCAP) ? fn : FCAP;
        for (int i = w; i < nf * 32; i += 8) {
            int e = i >> 5, kk = i & 31;
            unsigned int fl = sFl[e];
            int row = fl >> 2, q = fl & 3;
            int k = kk * 4 + (lane >> 3);
            int code = (k >> 1) * 8 + q * 2 + (k & 1);
            COOP_CHECK(row, code, 1)
        }
        if (fn > FCAP) {   // overflow fallback (practically never)
            for (int i = w; i < 128 * 128; i += 8) {
                int row = i >> 7, c4 = i & 127;
                int code = c4 * 4 + (lane >> 3);
                COOP_CHECK(row, code, 1)
            }
        }
    }
#undef COOP_CHECK
    __syncthreads();

    // ---- warp-cooperative epilogue: 8 lanes per position, lane d4 owns dims 4d4..4d4+3 ----
    float lloss = 0.0f;
    for (int it = 0; it < 4; it++) {
        const int pp = it * 32 + w * 4 + (lane >> 3);
        const int d4 = lane & 7;
        const int bi = (int)(sBest[pp] & 0xFFFFFFFFull);

        const int t = tile * 128 + pp;
        const int b = t >> 6, l = t & 63;

        // x dims 4d4+k live at slot k*8+d4 (conflict-free scalar LDS)
        const float* xr = sX + pp * 36 + d4;
        float x0 = xr[0], x1 = xr[8], x2 = xr[16], x3 = xr[24];
        // e dims 4d4+k at slot (k*8+d4) ^ ((bi&1)*4)
        const float* epb = sE + ((bi >> 3) << 8) + ((bi & 7) * 32);
        const int x4s = (bi & 1) * 4;
        float q0 = epb[(0 * 8 + d4) ^ x4s];
        float q1 = epb[(1 * 8 + d4) ^ x4s];
        float q2 = epb[(2 * 8 + d4) ^ x4s];
        float q3 = epb[(3 * 8 + d4) ^ x4s];

        float* zq = out + OFF_ZQ + (size_t)b * 8192 + (size_t)n * 2048 + l;
        zq[(4 * d4 + 0) * 64] = __fsub_rn(__fadd_rn(q0, x0), x0);
        zq[(4 * d4 + 1) * 64] = __fsub_rn(__fadd_rn(q1, x1), x1);
        zq[(4 * d4 + 2) * 64] = __fsub_rn(__fadd_rn(q2, x2), x2);
        zq[(4 * d4 + 3) * 64] = __fsub_rn(__fadd_rn(q3, x3), x3);

        float f0 = x0 - q0, f1 = x1 - q1, f2 = x2 - q2, f3 = x3 - q3;
        lloss = fmaf(f0, f0, lloss);
        lloss = fmaf(f1, f1, lloss);
        lloss = fmaf(f2, f2, lloss);
        lloss = fmaf(f3, f3, lloss);

        if (d4 == 0) {
            out[OFF_IDX + (size_t)b * 256 + (size_t)n * 64 + l] = (float)bi;
            atomicAdd(&g_counts[n * M_CODES + bi], 1);
        }
        atomicAdd(g_dw4 + ((size_t)n * M_CODES + bi) * 8 + d4,
                  make_float4(x0, x1, x2, x3));
    }

    // ---- CTA loss reduction -> one double atomic ----
#pragma unroll
    for (int o = 16; o > 0; o >>= 1) lloss += __shfl_down_sync(0xFFFFFFFFu, lloss, o);
    if (lane == 0) sWs[w] = lloss;
    __syncthreads();
    if (tid == 0) {
        double s = 0.0;
#pragma unroll
        for (int ww = 0; ww < 8; ww++) s += (double)sWs[ww];
        atomicAdd(&g_loss, s);
    }
}

// ---------------- kernel 2a: counts -> EMA count, Laplace, perplexity, loss ----------------
__global__ void vq_fin_a(const float* __restrict__ ema_c,
                         float* __restrict__ out) {
    const int n = blockIdx.x;
    const int m = threadIdx.x;
    __shared__ float red[M_CODES];

    const float DECAY = 0.999f;
    const float OMD   = (float)(1.0 - 0.999);
    const float MEPS  = (float)(512.0 * 1e-5);

    const int ci = n * M_CODES + m;
    float cnt  = (float)g_counts[ci];
    g_counts[ci] = 0;
    float cnew = DECAY * ema_c[ci] + OMD * cnt;

    red[m] = cnew;
    __syncthreads();
    for (int s = 256; s > 0; s >>= 1) {
        if (m < s) red[m] += red[m + s];
        __syncthreads();
    }
    float ntot = red[0];
    __syncthreads();

    float clap = (cnew + 1e-5f) / (ntot + MEPS) * ntot;
    out[OFF_CNT + (size_t)ci] = clap;
    g_clap[ci] = clap;

    float p    = cnt * (1.0f / 65536.0f);
    float term = p * logf(p + 1e-10f);
    red[m] = term;
    __syncthreads();
    for (int s = 256; s > 0; s >>= 1) {
        if (m < s) red[m] += red[m + s];
        __syncthreads();
    }
    if (m == 0) {
        atomicAdd(&out[OFF_PERP], expf(-red[0]));
        if (n == 0) {
            out[OFF_LOSS] = (float)(0.25 * g_loss * (1.0 / 8388608.0));
            g_loss = 0.0;
        }
    }
}

// ---------------- kernel 2b: coalesced weight/embedding update (chip-wide) ----------------
__global__ void vq_fin_b(const float* __restrict__ ema_w,
                         float* __restrict__ out) {
    const float DECAY = 0.999f;
    const float OMD   = (float)(1.0 - 0.999);
    float* g_dwf = (float*)g_dw4;

    const int i = blockIdx.x * 512 + threadIdx.x;
    float wv = DECAY * ema_w[i] + OMD * g_dwf[i];
    g_dwf[i] = 0.0f;
    out[OFF_W + (size_t)i]   = wv;
    out[OFF_EMB + (size_t)i] = wv / g_clap[i >> 5];
}

// ---------------- launch ----------------
extern "C" void kernel_launch(void* const* d_in, const int* in_sizes, int n_in,
                              void* d_out, int out_size) {
    const float* x     = (const float*)d_in[0];
    const float* emb   = (const float*)d_in[1];
    const float* ema_c = (const float*)d_in[2];
    const float* ema_w = (const float*)d_in[3];
    float* out = (float*)d_out;

    cudaFuncSetAttribute(vq_main, cudaFuncAttributeMaxDynamicSharedMemorySize, SMEM_BYTES);

    vq_main<<<dim3(T_POS / 128, N_CB), 256, SMEM_BYTES>>>(x, emb, out);
    vq_fin_a<<<N_CB, M_CODES>>>(ema_c, out);
    vq_fin_b<<<128, 512>>>(ema_w, out);
}

// round 17
// speedup vs baseline: 1.1832x; 1.1832x over previous
#include <cuda_runtime.h>
#include <cstdint>

// ---------------- problem constants ----------------
#define N_CB 4
#define M_CODES 512
#define D_DIM 32
#define T_POS 65536

// output layout (float32, reference tuple order, flattened+concatenated)
#define OFF_ZQ   0ULL
#define OFF_LOSS 8388608ULL
#define OFF_PERP 8388609ULL
#define OFF_IDX  8388610ULL
#define OFF_EMB  8650754ULL
#define OFF_CNT  8716290ULL
#define OFF_W    8718338ULL

// fragment-permuted slot: d = kt*8 + 4*h + q4  ->  slot = q4*8 + kt*2 + h
#define SLOT(d) (((d) & 3) * 8 + ((d) >> 3) * 2 + (((d) >> 2) & 1))

// ---------------- smem layout (float offsets), stride 36 rows ----------------
#define SXP_F   0        // x  [128 pos][36]  (permuted)   4608
#define SE_F    4608     // e' = -2e [512 code][36]       18432
#define SESQ_F  23040    // esq[512]
#define SXSQ_F  23552    // xsq[128]
#define SSAB_F  23680    // sum|x| [128]
#define SBEST_F 23808    // u64[128] packed (dist,code)
#define SFL_F   24064    // flag list u32[128]
#define SWS_F   24192    // warp loss partials [8]
#define SMEM_FLOATS 24200
#define SMEM_BYTES (SMEM_FLOATS * 4)   // 96800 -> 2 CTAs/SM

#define FLT_BIG 3.402823466e38f
#define MARG_COEF 1.6e-4f
#define MARG_ABS  5e-5f
#define FCAP 128

// ---------------- scratch (zero at load; finalize kernels re-zero after use) ----------------
__device__ int    g_counts[N_CB * M_CODES];
__device__ float4 g_dw4[N_CB * M_CODES * 8];
__device__ double g_loss;
__device__ float  g_clap[N_CB * M_CODES];

// ---------------- kernel 1: tf32 sweep (esq-folded accumulators), top-2, exact recheck ----------------
__global__ void __launch_bounds__(256) vq_main(const float* __restrict__ x,
                                               const float* __restrict__ emb,
                                               float* __restrict__ out) {
    extern __shared__ float sm[];
    __shared__ int fn;
    float* sX   = sm + SXP_F;
    float* sE   = sm + SE_F;          // holds -2e
    float* sEsq = sm + SESQ_F;
    float* sXsq = sm + SXSQ_F;
    float* sSab = sm + SSAB_F;
    unsigned long long* sBest = (unsigned long long*)(sm + SBEST_F);
    unsigned int* sFl = (unsigned int*)(sm + SFL_F);
    float* sWs  = sm + SWS_F;

    const int n    = blockIdx.y;
    const int tile = blockIdx.x;
    const int tid  = threadIdx.x;
    const int w    = tid >> 5;
    const int lane = tid & 31;
    const int g    = lane >> 2;
    const int q4   = lane & 3;

    if (tile == 0 && n == 0 && tid == 0) out[OFF_PERP] = 0.0f;

    // ---- fill x tile (permuted layout) ----
    for (int i = tid; i < 128 * D_DIM; i += 256) {
        int d = i >> 7, p = i & 127;
        int t = tile * 128 + p;
        sX[p * 36 + SLOT(d)] = x[(size_t)(t >> 6) * 8192 + (size_t)n * 2048 + d * 64 + (t & 63)];
    }
    // ---- fill codebook as -2e: fixed-d per thread, SLOT computed once, coalesced ----
    const float* en = emb + (size_t)n * M_CODES * D_DIM;
    {
        const int dfix  = tid & 31;
        const int slotf = SLOT(dfix);
        const int m0    = tid >> 5;     // 0..7
#pragma unroll 8
        for (int j = 0; j < 64; j++) {
            int m = m0 + j * 8;
            sE[m * 36 + slotf] = -2.0f * en[m * 32 + dfix];
        }
    }
    if (tid == 0) fn = 0;
    __syncthreads();

    // ---- esq: 0.25 * sum((e')^2) ascending d == original esq bitwise ----
    for (int c = tid; c < M_CODES; c += 256) {
        const float* er = sE + c * 36;
        float s = 0.0f;
#pragma unroll
        for (int d = 0; d < D_DIM; d++) {
            float v = er[SLOT(d)];
            s = fmaf(v, v, s);
        }
        sEsq[c] = 0.25f * s;
    }
    // ---- xsq + sum|x| + sBest init ----
    if (tid < 128) {
        const float* xr = sX + tid * 36;
        float s = 0.0f, a = 0.0f;
#pragma unroll
        for (int d = 0; d < D_DIM; d++) {
            float v = xr[SLOT(d)];
            s = fmaf(v, v, s);
            a += fabsf(v);
        }
        sXsq[tid] = s;
        sSab[tid] = a;
        sBest[tid] = 0xFFFFFFFFFFFFFFFFull;
    }
    __syncthreads();

    // ---- A fragments (4 x LDS.128 per thread) ----
    const int r0 = w * 16 + g;
    const int r1 = r0 + 8;
    float4 xa0 = *(const float4*)&sX[r0 * 36 + q4 * 8];
    float4 xa1 = *(const float4*)&sX[r0 * 36 + q4 * 8 + 4];
    float4 xb0 = *(const float4*)&sX[r1 * 36 + q4 * 8];
    float4 xb1 = *(const float4*)&sX[r1 * 36 + q4 * 8 + 4];
    float af0[4], af1[4], af2[4], af3[4];
    af0[0] = xa0.x; af2[0] = xa0.y; af0[1] = xa0.z; af2[1] = xa0.w;
    af0[2] = xa1.x; af2[2] = xa1.y; af0[3] = xa1.z; af2[3] = xa1.w;
    af1[0] = xb0.x; af3[0] = xb0.y; af1[1] = xb0.z; af3[1] = xb0.w;
    af1[2] = xb1.x; af3[2] = xb1.y; af1[3] = xb1.z; af3[3] = xb1.w;

    const float* peB = sE + g * 36 + q4 * 8;   // advances 288 per nt

    // ---- single branchless sweep; dist comes straight out of the accumulators ----
    float m1_0 = FLT_BIG, m2_0 = FLT_BIG, m1_1 = FLT_BIG, m2_1 = FLT_BIG;
    int   i1_0 = 0, i1_1 = 0;

#pragma unroll 4
    for (int nt = 0; nt < 64; nt++) {
        const int col0 = nt * 8 + q4 * 2;
        float2 e2 = *(const float2*)&sEsq[col0];
        // chain A initialized with esq; chain B with zero; dist = A + B
        float a0 = e2.x, a1 = e2.y, a2 = e2.x, a3 = e2.y;
        float b0 = 0.0f, b1 = 0.0f, b2 = 0.0f, b3 = 0.0f;
        {
            float4 e0 = *(const float4*)(peB + nt * 288);
            float4 e1 = *(const float4*)(peB + nt * 288 + 4);
            float bbf[8] = {e0.x, e0.y, e0.z, e0.w, e1.x, e1.y, e1.z, e1.w};
#pragma unroll
            for (int kt = 0; kt < 2; kt++) {
                asm volatile(
                    "mma.sync.aligned.m16n8k8.row.col.f32.tf32.tf32.f32 "
                    "{%0,%1,%2,%3}, {%4,%5,%6,%7}, {%8,%9}, {%0,%1,%2,%3};"
                    : "+f"(a0), "+f"(a1), "+f"(a2), "+f"(a3)
                    : "f"(af0[kt]), "f"(af1[kt]), "f"(af2[kt]), "f"(af3[kt]),
                      "f"(bbf[2 * kt]), "f"(bbf[2 * kt + 1]));
            }
#pragma unroll
            for (int kt = 2; kt < 4; kt++) {
                asm volatile(
                    "mma.sync.aligned.m16n8k8.row.col.f32.tf32.tf32.f32 "
                    "{%0,%1,%2,%3}, {%4,%5,%6,%7}, {%8,%9}, {%0,%1,%2,%3};"
                    : "+f"(b0), "+f"(b1), "+f"(b2), "+f"(b3)
                    : "f"(af0[kt]), "f"(af1[kt]), "f"(af2[kt]), "f"(af3[kt]),
                      "f"(bbf[2 * kt]), "f"(bbf[2 * kt + 1]));
            }
        }
        float d00 = a0 + b0;
        float d01 = a1 + b1;
        float d10 = a2 + b2;
        float d11 = a3 + b3;

        {   // row 0: branchless top-2 + index of min
            float lo = fminf(d00, d01);
            float hi = fmaxf(d00, d01);
            int  ilo = (d01 < d00) ? (col0 + 1) : col0;
            m2_0 = fminf(m2_0, fminf(hi, fmaxf(lo, m1_0)));
            i1_0 = (lo < m1_0) ? ilo : i1_0;
            m1_0 = fminf(m1_0, lo);
        }
        {   // row 1
            float lo = fminf(d10, d11);
            float hi = fmaxf(d10, d11);
            int  ilo = (d11 < d10) ? (col0 + 1) : col0;
            m2_1 = fminf(m2_1, fminf(hi, fmaxf(lo, m1_1)));
            i1_1 = (lo < m1_1) ? ilo : i1_1;
            m1_1 = fminf(m1_1, lo);
        }
    }

    const float lm1_0 = m1_0, lm2_0 = m2_0, lm1_1 = m1_1, lm2_1 = m2_1;
    const int   li1_0 = i1_0, li1_1 = i1_1;

    // ---- merge across the 4 quad-threads of each row ----
#pragma unroll
    for (int o = 1; o <= 2; o <<= 1) {
        float om1 = __shfl_xor_sync(0xFFFFFFFFu, m1_0, o);
        float om2 = __shfl_xor_sync(0xFFFFFFFFu, m2_0, o);
        m2_0 = fminf(fminf(m2_0, om2), fmaxf(m1_0, om1));
        m1_0 = fminf(m1_0, om1);
        float pm1 = __shfl_xor_sync(0xFFFFFFFFu, m1_1, o);
        float pm2 = __shfl_xor_sync(0xFFFFFFFFu, m2_1, o);
        m2_1 = fminf(fminf(m2_1, pm2), fmaxf(m1_1, pm1));
        m1_1 = fminf(m1_1, pm1);
    }
    const float thr0 = m1_0 + fmaf(sSab[r0], MARG_COEF, MARG_ABS);
    const float thr1 = m1_1 + fmaf(sSab[r1], MARG_COEF, MARG_ABS);

    // ---- exact fp32 recheck: dot' = sum x*(-2e); dist = dot' + (xsq + esq) ----
#define EXACT_CHECK(row, code) {                                                  \
        const float* xr = sX + (row) * 36;                                        \
        const float* er = sE + (code) * 36;                                       \
        float dot = 0.0f;                                                         \
        _Pragma("unroll")                                                         \
        for (int d = 0; d < D_DIM; d++)                                           \
            dot = fmaf(xr[SLOT(d)], er[SLOT(d)], dot);                            \
        float dist = dot + (sXsq[row] + sEsq[code]);                              \
        unsigned long long pk = ((unsigned long long)__float_as_uint(dist) << 32) \
                                | (unsigned int)(code);                           \
        atomicMin(&sBest[row], pk);                                               \
    }

    if (lm1_0 <= thr0) EXACT_CHECK(r0, li1_0)
    if (lm1_1 <= thr1) EXACT_CHECK(r1, li1_1)
    if (lm2_0 <= thr0) { int s = atomicAdd(&fn, 1); if (s < FCAP) sFl[s] = (r0 << 2) | q4; }
    if (lm2_1 <= thr1) { int s = atomicAdd(&fn, 1); if (s < FCAP) sFl[s] = (r1 << 2) | q4; }
    __syncthreads();

    // ---- cooperative exact rescan of flagged (row, quad) 128-code ranges ----
    {
        const int nf = (fn < FCAP) ? fn : FCAP;
        for (int i = tid; i < nf * 128; i += 256) {
            const int e = i >> 7, k = i & 127;
            const unsigned int fl = sFl[e];
            const int row = fl >> 2, q = fl & 3;
            const int code = (k >> 1) * 8 + q * 2 + (k & 1);
            EXACT_CHECK(row, code)
        }
        if (fn > FCAP) {   // overflow fallback (practically never)
            for (int i = tid; i < 128 * M_CODES; i += 256) {
                EXACT_CHECK(i >> 9, i & 511)
            }
        }
    }
#undef EXACT_CHECK
    __syncthreads();

    // ---- epilogue: outputs per position (q = -0.5 * e', exact original e bits) ----
    float lloss = 0.0f;
    if (tid < 128) {
        const int pp = tid;
        const int bi = (int)(sBest[pp] & 0xFFFFFFFFull);

        const int t = tile * 128 + pp;
        const int b = t >> 6, l = t & 63;
        out[OFF_IDX + (size_t)b * 256 + (size_t)n * 64 + l] = (float)bi;
        atomicAdd(&g_counts[n * M_CODES + bi], 1);

        float4* dwp = g_dw4 + ((size_t)n * M_CODES + bi) * 8;
        float*  zq  = out + OFF_ZQ + (size_t)b * 8192 + (size_t)n * 2048 + l;
        const float* xr = sX + pp * 36;
        const float* er = sE + bi * 36;
#pragma unroll
        for (int d4 = 0; d4 < 8; d4++) {
            float xv0 = xr[SLOT(d4 * 4 + 0)], q0 = -0.5f * er[SLOT(d4 * 4 + 0)];
            float xv1 = xr[SLOT(d4 * 4 + 1)], q1 = -0.5f * er[SLOT(d4 * 4 + 1)];
            float xv2 = xr[SLOT(d4 * 4 + 2)], q2 = -0.5f * er[SLOT(d4 * 4 + 2)];
            float xv3 = xr[SLOT(d4 * 4 + 3)], q3 = -0.5f * er[SLOT(d4 * 4 + 3)];
            zq[(d4 * 4 + 0) * 64] = __fsub_rn(__fadd_rn(q0, xv0), xv0);
            zq[(d4 * 4 + 1) * 64] = __fsub_rn(__fadd_rn(q1, xv1), xv1);
            zq[(d4 * 4 + 2) * 64] = __fsub_rn(__fadd_rn(q2, xv2), xv2);
            zq[(d4 * 4 + 3) * 64] = __fsub_rn(__fadd_rn(q3, xv3), xv3);
            float f0 = xv0 - q0, f1 = xv1 - q1, f2 = xv2 - q2, f3 = xv3 - q3;
            lloss = fmaf(f0, f0, lloss);
            lloss = fmaf(f1, f1, lloss);
            lloss = fmaf(f2, f2, lloss);
            lloss = fmaf(f3, f3, lloss);
            atomicAdd(dwp + d4, make_float4(xv0, xv1, xv2, xv3));
        }
    }

    // ---- CTA loss reduction -> one double atomic ----
#pragma unroll
    for (int o = 16; o > 0; o >>= 1) lloss += __shfl_down_sync(0xFFFFFFFFu, lloss, o);
    if (lane == 0) sWs[w] = lloss;
    __syncthreads();
    if (tid == 0) {
        double s = 0.0;
#pragma unroll
        for (int ww = 0; ww < 8; ww++) s += (double)sWs[ww];
        atomicAdd(&g_loss, s);
    }
}

// ---------------- kernel 2a: counts -> EMA count, Laplace, perplexity, loss ----------------
__global__ void vq_fin_a(const float* __restrict__ ema_c,
                         float* __restrict__ out) {
    const int n = blockIdx.x;
    const int m = threadIdx.x;
    __shared__ float red[M_CODES];

    const float DECAY = 0.999f;
    const float OMD   = (float)(1.0 - 0.999);
    const float MEPS  = (float)(512.0 * 1e-5);

    const int ci = n * M_CODES + m;
    float cnt  = (float)g_counts[ci];
    g_counts[ci] = 0;
    float cnew = DECAY * ema_c[ci] + OMD * cnt;

    red[m] = cnew;
    __syncthreads();
    for (int s = 256; s > 0; s >>= 1) {
        if (m < s) red[m] += red[m + s];
        __syncthreads();
    }
    float ntot = red[0];
    __syncthreads();

    float clap = (cnew + 1e-5f) / (ntot + MEPS) * ntot;
    out[OFF_CNT + (size_t)ci] = clap;
    g_clap[ci] = clap;

    float p    = cnt * (1.0f / 65536.0f);
    float term = p * logf(p + 1e-10f);
    red[m] = term;
    __syncthreads();
    for (int s = 256; s > 0; s >>= 1) {
        if (m < s) red[m] += red[m + s];
        __syncthreads();
    }
    if (m == 0) {
        atomicAdd(&out[OFF_PERP], expf(-red[0]));
        if (n == 0) {
            out[OFF_LOSS] = (float)(0.25 * g_loss * (1.0 / 8388608.0));
            g_loss = 0.0;
        }
    }
}

// ---------------- kernel 2b: coalesced weight/embedding update (chip-wide) ----------------
__global__ void vq_fin_b(const float* __restrict__ ema_w,
                         float* __restrict__ out) {
    const float DECAY = 0.999f;
    const float OMD   = (float)(1.0 - 0.999);
    float* g_dwf = (float*)g_dw4;

    const int i = blockIdx.x * 512 + threadIdx.x;
    float wv = DECAY * ema_w[i] + OMD * g_dwf[i];
    g_dwf[i] = 0.0f;
    out[OFF_W + (size_t)i]   = wv;
    out[OFF_EMB + (size_t)i] = wv / g_clap[i >> 5];
}

// ---------------- launch ----------------
extern "C" void kernel_launch(void* const* d_in, const int* in_sizes, int n_in,
                              void* d_out, int out_size) {
    const float* x     = (const float*)d_in[0];
    const float* emb   = (const float*)d_in[1];
    const float* ema_c = (const float*)d_in[2];
    const float* ema_w = (const float*)d_in[3];
    float* out = (float*)d_out;

    cudaFuncSetAttribute(vq_main, cudaFuncAttributeMaxDynamicSharedMemorySize, SMEM_BYTES);

    vq_main<<<dim3(T_POS / 128, N_CB), 256, SMEM_BYTES>>>(x, emb, out);
    vq_fin_a<<<N_CB, M_CODES>>>(ema_c, out);
    vq_fin_b<<<128, 512>>>(ema_w, out);
}